// round 9
// baseline (speedup 1.0000x reference)
#include <cuda_runtime.h>
#include <cuda_fp16.h>
#include <cstdint>

#define F_IN 256
#define F_OUT 64
#define MAX_N 100000
#define MAX_E 3200000

// Scratch (device globals — no allocation allowed)
__device__ __half g_h16[(size_t)MAX_N * F_OUT];
__device__ float  g_s1[MAX_N];
__device__ float  g_s2[MAX_N];
__device__ int    g_deg[MAX_N];
__device__ int    g_rowptr[MAX_N + 1];
__device__ int    g_rank[MAX_E];
__device__ int2   g_sdw[MAX_E];     // (dst, w as float bits), src-sorted
__device__ int    g_bsum[128];
__device__ int    g_is64;

// ---------------------------------------------------------------------------
// Detect edge_index dtype: int64 (odd 32-bit words all zero) vs int32.
// ---------------------------------------------------------------------------
__global__ void detect_kernel(const int* __restrict__ ei32) {
    int lane = threadIdx.x;
    int bad = 0;
    for (int i = lane; i < 64; i += 32)
        if (ei32[2 * i + 1] != 0) bad = 1;
    unsigned m = __ballot_sync(0xffffffffu, bad);
    if (lane == 0) g_is64 = (m == 0u);
}

__device__ __forceinline__ int edge_at(const int* ei32, int is64, long long idx) {
    return is64 ? ei32[2 * idx] : ei32[idx];   // little-endian low word
}

// ---------------------------------------------------------------------------
__global__ void zero_deg_kernel(int n) {
    int i = blockIdx.x * blockDim.x + threadIdx.x;
    if (i < n) g_deg[i] = 0;
}

// ---------------------------------------------------------------------------
// Packed f32x2 helpers (sm_100+ PTX; ptxas never auto-fuses FFMA2)
// ---------------------------------------------------------------------------
__device__ __forceinline__ unsigned long long pack_dup(float x) {
    unsigned long long r;
    unsigned u = __float_as_uint(x);
    asm("mov.b64 %0, {%1, %1};" : "=l"(r) : "r"(u));
    return r;
}
__device__ __forceinline__ void fma_f32x2(unsigned long long& acc,
                                          unsigned long long a,
                                          unsigned long long b) {
    asm("fma.rn.f32x2 %0, %1, %2, %0;" : "+l"(acc) : "l"(a), "l"(b));
}

// ---------------------------------------------------------------------------
// FUSED kernel: blocks [0, gemmBlocks) run the SGEMM (+s1/s2 epilogue);
// blocks [gemmBlocks, ...) run the edge-rank pass (histogram + rank).
// ---------------------------------------------------------------------------
__global__ __launch_bounds__(256) void gemm_rank_kernel(
    const float* __restrict__ X, const float* __restrict__ W,
    const float* __restrict__ a, const int* __restrict__ ei32,
    int M, int E, int gemmBlocks)
{
    __shared__ __align__(16) float Xs[32][132];
    __shared__ __align__(16) float Ws[32][64];

    if (blockIdx.x >= gemmBlocks) {
        // ---- rank path ----
        int e = (blockIdx.x - gemmBlocks) * 256 + threadIdx.x;
        if (e >= E) return;
        int is64 = g_is64;
        int src = edge_at(ei32, is64, e);
        int dst = edge_at(ei32, is64, (long long)E + e);
        int r = -1;
        if ((unsigned)src < (unsigned)M && (unsigned)dst < (unsigned)M)
            r = atomicAdd(&g_deg[src], 1);
        g_rank[e] = r;
        return;
    }

    // ---- gemm path ----
    int tid = threadIdx.x;
    int tx = tid & 15;   // col group: cols tx*4 .. tx*4+3
    int ty = tid >> 4;   // row group: rows ty*8 .. ty*8+7
    int m0 = blockIdx.x * 128;

    unsigned long long accp[4][4];
#pragma unroll
    for (int p = 0; p < 4; p++)
#pragma unroll
        for (int j = 0; j < 4; j++) accp[p][j] = 0ull;

    for (int k0 = 0; k0 < F_IN; k0 += 32) {
#pragma unroll
        for (int i = 0; i < 4; i++) {
            int idx = tid + i * 256;
            int r   = idx >> 3;
            int kc  = idx & 7;
            float4 v = make_float4(0.f, 0.f, 0.f, 0.f);
            int row = m0 + r;
            if (row < M)
                v = *(const float4*)(X + (size_t)row * F_IN + k0 + kc * 4);
            Xs[kc * 4 + 0][r] = v.x;
            Xs[kc * 4 + 1][r] = v.y;
            Xs[kc * 4 + 2][r] = v.z;
            Xs[kc * 4 + 3][r] = v.w;
        }
#pragma unroll
        for (int i = 0; i < 2; i++) {
            int idx = tid + i * 256;
            int kr  = idx >> 4;
            int c4  = idx & 15;
            float4 w = *(const float4*)(W + (size_t)(k0 + kr) * F_OUT + c4 * 4);
            *(float4*)&Ws[kr][c4 * 4] = w;
        }
        __syncthreads();

#pragma unroll
        for (int kk = 0; kk < 32; kk++) {
            float4 b = *(const float4*)&Ws[kk][tx * 4];
            unsigned long long bv0 = pack_dup(b.x);
            unsigned long long bv1 = pack_dup(b.y);
            unsigned long long bv2 = pack_dup(b.z);
            unsigned long long bv3 = pack_dup(b.w);
            unsigned long long av[4];
#pragma unroll
            for (int p = 0; p < 4; p++)
                av[p] = *(const unsigned long long*)&Xs[kk][ty * 8 + 2 * p];
#pragma unroll
            for (int p = 0; p < 4; p++) {
                fma_f32x2(accp[p][0], av[p], bv0);
                fma_f32x2(accp[p][1], av[p], bv1);
                fma_f32x2(accp[p][2], av[p], bv2);
                fma_f32x2(accp[p][3], av[p], bv3);
            }
        }
        __syncthreads();
    }

    float accf[8][4];
#pragma unroll
    for (int p = 0; p < 4; p++)
#pragma unroll
        for (int j = 0; j < 4; j++) {
            float2 f = *reinterpret_cast<float2*>(&accp[p][j]);
            accf[2 * p][j]     = f.x;
            accf[2 * p + 1][j] = f.y;
        }

    // Store h as fp16
#pragma unroll
    for (int i = 0; i < 8; i++) {
        int row = m0 + ty * 8 + i;
        if (row < M) {
            __half2 lo = __floats2half2_rn(accf[i][0], accf[i][1]);
            __half2 hi = __floats2half2_rn(accf[i][2], accf[i][3]);
            uint2 pkt = make_uint2(*(unsigned*)&lo, *(unsigned*)&hi);
            *(uint2*)(g_h16 + (size_t)row * F_OUT + tx * 4) = pkt;
        }
    }

    // Fused s1/s2 epilogue (fp32, exact)
    float a1v[4], a2v[4];
#pragma unroll
    for (int j = 0; j < 4; j++) {
        a1v[j] = __ldg(a + tx * 4 + j);
        a2v[j] = __ldg(a + 64 + tx * 4 + j);
    }
    float s1p[8], s2p[8];
#pragma unroll
    for (int i = 0; i < 8; i++) {
        float t1 = 0.f, t2 = 0.f;
#pragma unroll
        for (int j = 0; j < 4; j++) {
            t1 = fmaf(accf[i][j], a1v[j], t1);
            t2 = fmaf(accf[i][j], a2v[j], t2);
        }
        s1p[i] = t1; s2p[i] = t2;
    }
#pragma unroll
    for (int o = 1; o < 16; o <<= 1) {
#pragma unroll
        for (int i = 0; i < 8; i++) {
            s1p[i] += __shfl_xor_sync(0xffffffffu, s1p[i], o);
            s2p[i] += __shfl_xor_sync(0xffffffffu, s2p[i], o);
        }
    }
    if (tx == 0) {
#pragma unroll
        for (int i = 0; i < 8; i++) {
            int row = m0 + ty * 8 + i;
            if (row < M) { g_s1[row] = s1p[i]; g_s2[row] = s2p[i]; }
        }
    }
}

// ---------------------------------------------------------------------------
// Scan (rowptr from deg)
// ---------------------------------------------------------------------------
__global__ void scan1_kernel(int n) {
    __shared__ int s[1024];
    int i = blockIdx.x * 1024 + threadIdx.x;
    int v = (i < n) ? g_deg[i] : 0;
    s[threadIdx.x] = v;
    __syncthreads();
#pragma unroll
    for (int o = 1; o < 1024; o <<= 1) {
        int t = (threadIdx.x >= o) ? s[threadIdx.x - o] : 0;
        __syncthreads();
        s[threadIdx.x] += t;
        __syncthreads();
    }
    if (i < n) g_rowptr[i + 1] = s[threadIdx.x];
    if (threadIdx.x == 1023) g_bsum[blockIdx.x] = s[1023];
}

__global__ void scan2_kernel(int nb) {
    __shared__ int s[128];
    int v = (threadIdx.x < nb) ? g_bsum[threadIdx.x] : 0;
    s[threadIdx.x] = v;
    __syncthreads();
#pragma unroll
    for (int o = 1; o < 128; o <<= 1) {
        int t = (threadIdx.x >= o) ? s[threadIdx.x - o] : 0;
        __syncthreads();
        s[threadIdx.x] += t;
        __syncthreads();
    }
    if (threadIdx.x < nb) g_bsum[threadIdx.x] = s[threadIdx.x] - v;
}

__global__ void scan3_kernel(int n) {
    int i = blockIdx.x * blockDim.x + threadIdx.x;
    if (i < n) g_rowptr[i + 1] += g_bsum[i >> 10];
    if (i == 0) g_rowptr[0] = 0;
}

// ---------------------------------------------------------------------------
// Scatter: atomic-free (uses precomputed ranks). ALSO precomputes the edge
// weight w = exp(lrelu(s1[src]+s2[dst])) here — scatter is latency-tolerant,
// and this removes the s2 gather + exp from the aggregate's critical path.
// (global-max subtraction cancels analytically; skipped)
// ---------------------------------------------------------------------------
__global__ void scatter_kernel(const int* __restrict__ ei32, int E, int M) {
    int e = blockIdx.x * blockDim.x + threadIdx.x;
    if (e >= E) return;
    int r = g_rank[e];
    if (r < 0) return;
    int is64 = g_is64;
    int src = edge_at(ei32, is64, e);
    int dst = edge_at(ei32, is64, (long long)E + e);
    float v  = g_s1[src] + g_s2[dst];
    float ev = v > 0.0f ? v : 0.2f * v;
    float w  = __expf(ev);
    g_sdw[g_rowptr[src] + r] = make_int2(dst, __float_as_int(w));
}

// ---------------------------------------------------------------------------
// Aggregate + finalize: one warp per node, eg groups of 8 lanes, 8 feats/lane.
// (dst, w) pairs are precomputed; only dependent load per edge is the h16
// gather. Unrolled x2 with dual prefetch -> 2 independent gathers in flight.
// ---------------------------------------------------------------------------
__global__ void aggregate_kernel(float* __restrict__ out, int M) {
    int node = (blockIdx.x * blockDim.x + threadIdx.x) >> 5;
    if (node >= M) return;
    int lane = threadIdx.x & 31;
    int sub  = lane & 7;    // feature group: features sub*8 .. sub*8+7
    int eg   = lane >> 3;   // edge group 0..3

    int beg = g_rowptr[node];
    int end = g_rowptr[node + 1];

    float acc[8];
#pragma unroll
    for (int j = 0; j < 8; j++) acc[j] = 0.0f;
    float wsum = 0.0f;

    int p = beg + eg;
    // 2-slot pipeline: both (dst,w) pairs fetched before either h gather
    int2 c0 = (p < end)     ? g_sdw[p]     : make_int2(0, 0);
    int2 c1 = (p + 4 < end) ? g_sdw[p + 4] : make_int2(0, 0);

    for (; p < end; p += 8) {
        int2 n0 = (p + 8  < end) ? g_sdw[p + 8]  : make_int2(0, 0);
        int2 n1 = (p + 12 < end) ? g_sdw[p + 12] : make_int2(0, 0);

        // slot 0
        {
            uint4 q = *(const uint4*)(g_h16 + (size_t)c0.x * F_OUT + sub * 8);
            float w = __int_as_float(c0.y);
            // second gather issued before consuming first (independent)
            uint4 q1 = make_uint4(0, 0, 0, 0);
            bool has1 = (p + 4 < end);
            if (has1) q1 = *(const uint4*)(g_h16 + (size_t)c1.x * F_OUT + sub * 8);

            wsum += w;
            float2 f0 = __half22float2(*(const __half2*)&q.x);
            float2 f1 = __half22float2(*(const __half2*)&q.y);
            float2 f2 = __half22float2(*(const __half2*)&q.z);
            float2 f3 = __half22float2(*(const __half2*)&q.w);
            acc[0] = fmaf(w, f0.x, acc[0]);
            acc[1] = fmaf(w, f0.y, acc[1]);
            acc[2] = fmaf(w, f1.x, acc[2]);
            acc[3] = fmaf(w, f1.y, acc[3]);
            acc[4] = fmaf(w, f2.x, acc[4]);
            acc[5] = fmaf(w, f2.y, acc[5]);
            acc[6] = fmaf(w, f3.x, acc[6]);
            acc[7] = fmaf(w, f3.y, acc[7]);

            if (has1) {
                float w1 = __int_as_float(c1.y);
                wsum += w1;
                float2 g0 = __half22float2(*(const __half2*)&q1.x);
                float2 g1 = __half22float2(*(const __half2*)&q1.y);
                float2 g2 = __half22float2(*(const __half2*)&q1.z);
                float2 g3 = __half22float2(*(const __half2*)&q1.w);
                acc[0] = fmaf(w1, g0.x, acc[0]);
                acc[1] = fmaf(w1, g0.y, acc[1]);
                acc[2] = fmaf(w1, g1.x, acc[2]);
                acc[3] = fmaf(w1, g1.y, acc[3]);
                acc[4] = fmaf(w1, g2.x, acc[4]);
                acc[5] = fmaf(w1, g2.y, acc[5]);
                acc[6] = fmaf(w1, g3.x, acc[6]);
                acc[7] = fmaf(w1, g3.y, acc[7]);
            }
        }
        c0 = n0; c1 = n1;
    }

#pragma unroll
    for (int j = 0; j < 8; j++) {
        acc[j] += __shfl_xor_sync(0xffffffffu, acc[j], 8);
        acc[j] += __shfl_xor_sync(0xffffffffu, acc[j], 16);
    }
    wsum += __shfl_xor_sync(0xffffffffu, wsum, 8);
    wsum += __shfl_xor_sync(0xffffffffu, wsum, 16);

    if (eg == 0) {
        float inv = 1.0f / (wsum + 1e-15f);
        float o[8];
#pragma unroll
        for (int j = 0; j < 8; j++) {
            float hp = acc[j] * inv;
            o[j] = hp > 0.0f ? hp : expm1f(hp);
        }
        float* dst = out + (size_t)node * F_OUT + sub * 8;
        *(float4*)(dst)     = make_float4(o[0], o[1], o[2], o[3]);
        *(float4*)(dst + 4) = make_float4(o[4], o[5], o[6], o[7]);
    }
}

// ---------------------------------------------------------------------------
extern "C" void kernel_launch(void* const* d_in, const int* in_sizes, int n_in,
                              void* d_out, int out_size) {
    // Identify inputs by element count (robust to metadata ordering)
    int idx[4] = {0, 1, 2, 3};
    for (int i = 1; i < 4 && i < n_in; i++) {
        int k = idx[i], j = i - 1;
        while (j >= 0 && in_sizes[idx[j]] < in_sizes[k]) { idx[j + 1] = idx[j]; j--; }
        idx[j + 1] = k;
    }
    const float* X    = (const float*)d_in[idx[0]];
    const int*   ei32 = (const int*)d_in[idx[1]];
    const float* W    = (const float*)d_in[idx[2]];
    const float* a    = (const float*)d_in[idx[3]];
    float*       out  = (float*)d_out;

    int M = in_sizes[idx[0]] / F_IN;   // 100000
    int E = in_sizes[idx[1]] / 2;      // 3200000

    detect_kernel<<<1, 32>>>(ei32);
    zero_deg_kernel<<<(M + 511) / 512, 512>>>(M);

    int gemmBlocks = (M + 127) / 128;
    int rankBlocks = (E + 255) / 256;
    gemm_rank_kernel<<<gemmBlocks + rankBlocks, 256>>>(X, W, a, ei32, M, E, gemmBlocks);

    int nblk = (M + 1023) / 1024;
    scan1_kernel<<<nblk, 1024>>>(M);
    scan2_kernel<<<1, 128>>>(nblk);
    scan3_kernel<<<(M + 255) / 256, 256>>>(M);
    scatter_kernel<<<(E + 255) / 256, 256>>>(ei32, E, M);

    aggregate_kernel<<<(M * 32 + 255) / 256, 256>>>(out, M);
}

// round 11
// speedup vs baseline: 1.0328x; 1.0328x over previous
#include <cuda_runtime.h>
#include <cuda_fp16.h>
#include <cuda_bf16.h>
#include <cstdint>

#define F_IN 256
#define F_OUT 64
#define MAX_N 100000
#define MAX_E 3200000
#define TILE_M 128
#define KC 64            // K chunk staged in smem
#define XS_STRIDE 72     // bf16 elems per row (64 + 8 pad: conflict-free frags)

// Scratch (device globals — no allocation allowed)
__device__ __half g_h16[(size_t)MAX_N * F_OUT];
__device__ float  g_s1[MAX_N];
__device__ float  g_s2[MAX_N];
__device__ int    g_deg[MAX_N];
__device__ int    g_rowptr[MAX_N + 1];
__device__ int    g_rank[MAX_E];
__device__ int    g_sdst[MAX_E];
__device__ int    g_bsum[128];
__device__ int    g_is64;

// Dynamic smem layout (bytes)
#define SM_XHI 0
#define SM_XLO (SM_XHI + TILE_M * XS_STRIDE * 2)        // 18432
#define SM_WHI (SM_XLO + TILE_M * XS_STRIDE * 2)        // 36864
#define SM_WLO (SM_WHI + F_OUT * XS_STRIDE * 2)         // 46080
#define SM_AV  (SM_WLO + F_OUT * XS_STRIDE * 2)         // 55296
#define SM_TOTAL (SM_AV + 512)                           // 55808

// ---------------------------------------------------------------------------
// init: detect edge dtype (block 0, warp 0) + zero deg (all blocks)
// ---------------------------------------------------------------------------
__global__ void init_kernel(const int* __restrict__ ei32, int M) {
    if (blockIdx.x == 0 && threadIdx.x < 32) {
        int lane = threadIdx.x;
        int bad = 0;
        for (int i = lane; i < 64; i += 32)
            if (ei32[2 * i + 1] != 0) bad = 1;
        unsigned m = __ballot_sync(0xffffffffu, bad);
        if (lane == 0) g_is64 = (m == 0u);
    }
    int i = blockIdx.x * blockDim.x + threadIdx.x;
    if (i < M) g_deg[i] = 0;
}

__device__ __forceinline__ int edge_at(const int* ei32, int is64, long long idx) {
    return is64 ? ei32[2 * idx] : ei32[idx];   // little-endian low word
}

// ---------------------------------------------------------------------------
__device__ __forceinline__ void mma_bf16(float* c, const unsigned* a, const unsigned* b) {
    asm volatile(
        "mma.sync.aligned.m16n8k16.row.col.f32.bf16.bf16.f32 "
        "{%0,%1,%2,%3}, {%4,%5,%6,%7}, {%8,%9}, {%0,%1,%2,%3};"
        : "+f"(c[0]), "+f"(c[1]), "+f"(c[2]), "+f"(c[3])
        : "r"(a[0]), "r"(a[1]), "r"(a[2]), "r"(a[3]), "r"(b[0]), "r"(b[1]));
}

__device__ __forceinline__ unsigned bf16_hi2(float x, float y,
                                             unsigned& lo2) {
    __nv_bfloat16 hx = __float2bfloat16(x), hy = __float2bfloat16(y);
    __nv_bfloat16 lx = __float2bfloat16(x - __bfloat162float(hx));
    __nv_bfloat16 ly = __float2bfloat16(y - __bfloat162float(hy));
    __nv_bfloat162 h = __halves2bfloat162(hx, hy);
    __nv_bfloat162 l = __halves2bfloat162(lx, ly);
    lo2 = *(unsigned*)&l;
    return *(unsigned*)&h;
}

// ---------------------------------------------------------------------------
// FUSED kernel: blocks [0, gemmBlocks) = bf16-split mma.sync GEMM + s1/s2;
// blocks [gemmBlocks, ...) = edge-rank pass. (Fusion hides rank's latency.)
// ---------------------------------------------------------------------------
__global__ __launch_bounds__(256) void gemm_rank_kernel(
    const float* __restrict__ X, const float* __restrict__ W,
    const float* __restrict__ a, const int* __restrict__ ei32,
    int M, int E, int gemmBlocks)
{
    extern __shared__ __align__(16) char smem[];

    if (blockIdx.x >= gemmBlocks) {
        // ---- rank path ----
        int e = (blockIdx.x - gemmBlocks) * 256 + threadIdx.x;
        if (e >= E) return;
        int is64 = g_is64;
        int src = edge_at(ei32, is64, e);
        int dst = edge_at(ei32, is64, (long long)E + e);
        int r = -1;
        if ((unsigned)src < (unsigned)M && (unsigned)dst < (unsigned)M)
            r = atomicAdd(&g_deg[src], 1);
        g_rank[e] = r;
        return;
    }

    // ---- gemm path ----
    int tid  = threadIdx.x;
    int wid  = tid >> 5;           // 0..7 : rows wid*16 .. wid*16+15
    int lane = tid & 31;
    int gq   = lane >> 2;          // group 0..7
    int tq   = lane & 3;           // thread-in-group
    int m0   = blockIdx.x * TILE_M;
    int wrow = wid * 16;

    // stage a[]
    if (tid < 128) *(float*)(smem + SM_AV + tid * 4) = __ldg(a + tid);

    float acc[8][4];
#pragma unroll
    for (int nt = 0; nt < 8; nt++)
#pragma unroll
        for (int j = 0; j < 4; j++) acc[nt][j] = 0.0f;

    for (int kc = 0; kc < F_IN; kc += KC) {
        // ---- stage X chunk (hi/lo split), 128 x 64 bf16, stride 72
        for (int idx = tid; idx < TILE_M * (KC / 4); idx += 256) {
            int r  = idx >> 4;
            int c  = (idx & 15) * 4;
            int row = m0 + r;
            float4 v = make_float4(0.f, 0.f, 0.f, 0.f);
            if (row < M) v = *(const float4*)(X + (size_t)row * F_IN + kc + c);
            unsigned l0, l1;
            unsigned h0 = bf16_hi2(v.x, v.y, l0);
            unsigned h1 = bf16_hi2(v.z, v.w, l1);
            int off = (r * XS_STRIDE + c) * 2;
            *(uint2*)(smem + SM_XHI + off) = make_uint2(h0, h1);
            *(uint2*)(smem + SM_XLO + off) = make_uint2(l0, l1);
        }
        // ---- stage W chunk as Wt[n][k] (hi/lo), 64 x 64 bf16, stride 72
        for (int idx4 = tid; idx4 < (KC * F_OUT / 4); idx4 += 256) {
            int k  = idx4 >> 4;
            int n0 = (idx4 & 15) * 4;
            float4 v = *(const float4*)(W + (size_t)(kc + k) * F_OUT + n0);
            float vv[4] = {v.x, v.y, v.z, v.w};
#pragma unroll
            for (int j = 0; j < 4; j++) {
                __nv_bfloat16 h = __float2bfloat16(vv[j]);
                __nv_bfloat16 l = __float2bfloat16(vv[j] - __bfloat162float(h));
                int off = ((n0 + j) * XS_STRIDE + k) * 2;
                *(__nv_bfloat16*)(smem + SM_WHI + off) = h;
                *(__nv_bfloat16*)(smem + SM_WLO + off) = l;
            }
        }
        __syncthreads();

        // ---- mma over 4 k16-steps
#pragma unroll
        for (int ks = 0; ks < 4; ks++) {
            int k0 = ks * 16;
            unsigned ah[4], al[4];
            {
                int r0 = wrow + gq, r1 = wrow + gq + 8;
                int c0 = k0 + tq * 2, c1 = k0 + tq * 2 + 8;
                ah[0] = *(unsigned*)(smem + SM_XHI + (r0 * XS_STRIDE + c0) * 2);
                ah[1] = *(unsigned*)(smem + SM_XHI + (r1 * XS_STRIDE + c0) * 2);
                ah[2] = *(unsigned*)(smem + SM_XHI + (r0 * XS_STRIDE + c1) * 2);
                ah[3] = *(unsigned*)(smem + SM_XHI + (r1 * XS_STRIDE + c1) * 2);
                al[0] = *(unsigned*)(smem + SM_XLO + (r0 * XS_STRIDE + c0) * 2);
                al[1] = *(unsigned*)(smem + SM_XLO + (r1 * XS_STRIDE + c0) * 2);
                al[2] = *(unsigned*)(smem + SM_XLO + (r0 * XS_STRIDE + c1) * 2);
                al[3] = *(unsigned*)(smem + SM_XLO + (r1 * XS_STRIDE + c1) * 2);
            }
#pragma unroll
            for (int nt = 0; nt < 8; nt++) {
                int n = nt * 8 + gq;
                int c0 = k0 + tq * 2, c1 = k0 + tq * 2 + 8;
                unsigned bh[2], bl[2];
                bh[0] = *(unsigned*)(smem + SM_WHI + (n * XS_STRIDE + c0) * 2);
                bh[1] = *(unsigned*)(smem + SM_WHI + (n * XS_STRIDE + c1) * 2);
                bl[0] = *(unsigned*)(smem + SM_WLO + (n * XS_STRIDE + c0) * 2);
                bl[1] = *(unsigned*)(smem + SM_WLO + (n * XS_STRIDE + c1) * 2);
                mma_bf16(acc[nt], ah, bh);
                mma_bf16(acc[nt], ah, bl);
                mma_bf16(acc[nt], al, bh);
            }
        }
        __syncthreads();
    }

    // ---- epilogue: fp16 h store + s1/s2 (rows wrow+gq and wrow+gq+8)
    int rowA = m0 + wrow + gq;
    int rowB = rowA + 8;
    const float* as = (const float*)(smem + SM_AV);

    float s1A = 0.f, s2A = 0.f, s1B = 0.f, s2B = 0.f;
#pragma unroll
    for (int nt = 0; nt < 8; nt++) {
        int n = nt * 8 + tq * 2;
        float a10 = as[n], a11 = as[n + 1];
        float a20 = as[64 + n], a21 = as[64 + n + 1];
        s1A = fmaf(acc[nt][0], a10, fmaf(acc[nt][1], a11, s1A));
        s2A = fmaf(acc[nt][0], a20, fmaf(acc[nt][1], a21, s2A));
        s1B = fmaf(acc[nt][2], a10, fmaf(acc[nt][3], a11, s1B));
        s2B = fmaf(acc[nt][2], a20, fmaf(acc[nt][3], a21, s2B));
    }
    s1A += __shfl_xor_sync(0xffffffffu, s1A, 1); s1A += __shfl_xor_sync(0xffffffffu, s1A, 2);
    s2A += __shfl_xor_sync(0xffffffffu, s2A, 1); s2A += __shfl_xor_sync(0xffffffffu, s2A, 2);
    s1B += __shfl_xor_sync(0xffffffffu, s1B, 1); s1B += __shfl_xor_sync(0xffffffffu, s1B, 2);
    s2B += __shfl_xor_sync(0xffffffffu, s2B, 1); s2B += __shfl_xor_sync(0xffffffffu, s2B, 2);
    if (tq == 0) {
        if (rowA < M) { g_s1[rowA] = s1A; g_s2[rowA] = s2A; }
        if (rowB < M) { g_s1[rowB] = s1B; g_s2[rowB] = s2B; }
    }

    if (rowA < M) {
        __half* hr = g_h16 + (size_t)rowA * F_OUT;
#pragma unroll
        for (int nt = 0; nt < 8; nt++) {
            __half2 h = __floats2half2_rn(acc[nt][0], acc[nt][1]);
            *(unsigned*)(hr + nt * 8 + tq * 2) = *(unsigned*)&h;
        }
    }
    if (rowB < M) {
        __half* hr = g_h16 + (size_t)rowB * F_OUT;
#pragma unroll
        for (int nt = 0; nt < 8; nt++) {
            __half2 h = __floats2half2_rn(acc[nt][2], acc[nt][3]);
            *(unsigned*)(hr + nt * 8 + tq * 2) = *(unsigned*)&h;
        }
    }
}

// ---------------------------------------------------------------------------
// Scan (rowptr from deg)
// ---------------------------------------------------------------------------
__global__ void scan1_kernel(int n) {
    __shared__ int s[1024];
    int i = blockIdx.x * 1024 + threadIdx.x;
    int v = (i < n) ? g_deg[i] : 0;
    s[threadIdx.x] = v;
    __syncthreads();
#pragma unroll
    for (int o = 1; o < 1024; o <<= 1) {
        int t = (threadIdx.x >= o) ? s[threadIdx.x - o] : 0;
        __syncthreads();
        s[threadIdx.x] += t;
        __syncthreads();
    }
    if (i < n) g_rowptr[i + 1] = s[threadIdx.x];
    if (threadIdx.x == 1023) g_bsum[blockIdx.x] = s[1023];
}

__global__ void scan2_kernel(int nb) {
    __shared__ int s[128];
    int v = (threadIdx.x < nb) ? g_bsum[threadIdx.x] : 0;
    s[threadIdx.x] = v;
    __syncthreads();
#pragma unroll
    for (int o = 1; o < 128; o <<= 1) {
        int t = (threadIdx.x >= o) ? s[threadIdx.x - o] : 0;
        __syncthreads();
        s[threadIdx.x] += t;
        __syncthreads();
    }
    if (threadIdx.x < nb) g_bsum[threadIdx.x] = s[threadIdx.x] - v;
}

__global__ void scan3_kernel(int n) {
    int i = blockIdx.x * blockDim.x + threadIdx.x;
    if (i < n) g_rowptr[i + 1] += g_bsum[i >> 10];
    if (i == 0) g_rowptr[0] = 0;
}

// ---------------------------------------------------------------------------
// Scatter: atomic-free using precomputed ranks
// ---------------------------------------------------------------------------
__global__ void scatter_kernel(const int* __restrict__ ei32, int E, int M) {
    int e = blockIdx.x * blockDim.x + threadIdx.x;
    if (e >= E) return;
    int r = g_rank[e];
    if (r < 0) return;
    int is64 = g_is64;
    int src = edge_at(ei32, is64, e);
    int dst = edge_at(ei32, is64, (long long)E + e);
    g_sdst[g_rowptr[src] + r] = dst;
}

// ---------------------------------------------------------------------------
// Aggregate + finalize (R7 form): one warp per node, 4 edges in flight,
// 8 feats/lane, prefetch next sdst. Fused rowsum-divide + ELU.
// w = exp(lrelu(s1[src]+s2[dst]))   (global-max subtraction cancels; skipped)
// ---------------------------------------------------------------------------
__global__ void aggregate_kernel(float* __restrict__ out, int M) {
    int node = (blockIdx.x * blockDim.x + threadIdx.x) >> 5;
    if (node >= M) return;
    int lane = threadIdx.x & 31;
    int sub  = lane & 7;
    int eg   = lane >> 3;

    int beg = g_rowptr[node];
    int end = g_rowptr[node + 1];
    float s1v = g_s1[node];

    float acc[8];
#pragma unroll
    for (int j = 0; j < 8; j++) acc[j] = 0.0f;
    float wsum = 0.0f;

    int p = beg + eg;
    int dst_cur = (p < end) ? g_sdst[p] : 0;
    for (; p < end; p += 4) {
        int pn = p + 4;
        int dst_next = (pn < end) ? g_sdst[pn] : 0;   // prefetch

        float s2v = g_s2[dst_cur];
        uint4 q = *(const uint4*)(g_h16 + (size_t)dst_cur * F_OUT + sub * 8);

        float v  = s1v + s2v;
        float ev = v > 0.0f ? v : 0.2f * v;
        float w  = __expf(ev);
        wsum += w;

        float2 f0 = __half22float2(*(const __half2*)&q.x);
        float2 f1 = __half22float2(*(const __half2*)&q.y);
        float2 f2 = __half22float2(*(const __half2*)&q.z);
        float2 f3 = __half22float2(*(const __half2*)&q.w);
        acc[0] = fmaf(w, f0.x, acc[0]);
        acc[1] = fmaf(w, f0.y, acc[1]);
        acc[2] = fmaf(w, f1.x, acc[2]);
        acc[3] = fmaf(w, f1.y, acc[3]);
        acc[4] = fmaf(w, f2.x, acc[4]);
        acc[5] = fmaf(w, f2.y, acc[5]);
        acc[6] = fmaf(w, f3.x, acc[6]);
        acc[7] = fmaf(w, f3.y, acc[7]);

        dst_cur = dst_next;
    }

#pragma unroll
    for (int j = 0; j < 8; j++) {
        acc[j] += __shfl_xor_sync(0xffffffffu, acc[j], 8);
        acc[j] += __shfl_xor_sync(0xffffffffu, acc[j], 16);
    }
    wsum += __shfl_xor_sync(0xffffffffu, wsum, 8);
    wsum += __shfl_xor_sync(0xffffffffu, wsum, 16);

    if (eg == 0) {
        float inv = 1.0f / (wsum + 1e-15f);
        float o[8];
#pragma unroll
        for (int j = 0; j < 8; j++) {
            float hp = acc[j] * inv;
            o[j] = hp > 0.0f ? hp : expm1f(hp);
        }
        float* dst = out + (size_t)node * F_OUT + sub * 8;
        *(float4*)(dst)     = make_float4(o[0], o[1], o[2], o[3]);
        *(float4*)(dst + 4) = make_float4(o[4], o[5], o[6], o[7]);
    }
}

// ---------------------------------------------------------------------------
extern "C" void kernel_launch(void* const* d_in, const int* in_sizes, int n_in,
                              void* d_out, int out_size) {
    // Identify inputs by element count (robust to metadata ordering)
    int idx[4] = {0, 1, 2, 3};
    for (int i = 1; i < 4 && i < n_in; i++) {
        int k = idx[i], j = i - 1;
        while (j >= 0 && in_sizes[idx[j]] < in_sizes[k]) { idx[j + 1] = idx[j]; j--; }
        idx[j + 1] = k;
    }
    const float* X    = (const float*)d_in[idx[0]];
    const int*   ei32 = (const int*)d_in[idx[1]];
    const float* W    = (const float*)d_in[idx[2]];
    const float* a    = (const float*)d_in[idx[3]];
    float*       out  = (float*)d_out;

    int M = in_sizes[idx[0]] / F_IN;   // 100000
    int E = in_sizes[idx[1]] / 2;      // 3200000

    init_kernel<<<(M + 511) / 512, 512>>>(ei32, M);

    int gemmBlocks = (M + TILE_M - 1) / TILE_M;
    int rankBlocks = (E + 255) / 256;
    cudaFuncSetAttribute(gemm_rank_kernel,
                         cudaFuncAttributeMaxDynamicSharedMemorySize, SM_TOTAL);
    gemm_rank_kernel<<<gemmBlocks + rankBlocks, 256, SM_TOTAL>>>(
        X, W, a, ei32, M, E, gemmBlocks);

    int nblk = (M + 1023) / 1024;
    scan1_kernel<<<nblk, 1024>>>(M);
    scan2_kernel<<<1, 128>>>(nblk);
    scan3_kernel<<<(M + 255) / 256, 256>>>(M);
    scatter_kernel<<<(E + 255) / 256, 256>>>(ei32, E, M);

    aggregate_kernel<<<(M * 32 + 255) / 256, 256>>>(out, M);
}